// round 17
// baseline (speedup 1.0000x reference)
#include <cuda_runtime.h>
#include <cuda_bf16.h>

// TD loss backward recurrence, T=256, B=65536. FINAL — session argmax,
// reproduced 5x (R11/R13/R14/R16 + R15 .wt twin): wall 80.35-80.64us,
// kernel 77.5-78.3us, DRAM 84.6-85.4%, 6.70-6.77 TB/s = ~98% of the
// path-independent ~6300 B/cyc LTS structural cap. Converged.
//
// Design (15 measured rounds):
//  - float2 loads (LDG.64): 32b -> 39-62% DRAM; 128b -> 72.6%; 64b -> 85%.
//  - BATCH=4 double-buffered prefetch: 28 LDG.64 continuously in flight/warp
//    (phase-alternating: 69.5%; triple buffer: 254-reg wall, regression).
//  - __launch_bounds__(64,1): lifts ptxas' 32-reg cap (the original MLP
//    killer); 168 regs, inside the 120-200 flat optimum.
//  - default loads (+2% vs .cs: cross-warp same-128B-line L2 reuse) +
//    .cs stores (+1% vs default; == .wt).
//  - Warp count at fixed width: both directions regress; 6.9 warps/SM opt.
// Compute pipes <7% busy; traffic provably minimal (537 MB, one touch/elem).

#define TD_T 256
#define TD_GAMMA 0.99f
#define BATCH 4
#define NBATCH 63   // batches cover t = 251 .. 0

struct Buf {
    float2 d[BATCH], r[BATCH], tv[BATCH], vl[BATCH];
    int2   st[BATCH], rb[BATCH], tn[BATCH];
};

__device__ __forceinline__ void load_batch(
    Buf& bf, int j, int p, int P,
    const float2* __restrict__ rw2, const float2* __restrict__ dc2,
    const float2* __restrict__ vl2, const float2* __restrict__ tv2,
    const int2* __restrict__ st2, const int2* __restrict__ rb2,
    const int2* __restrict__ tb2)
{
    const int tb_hi = 251 - 4 * j;
    #pragma unroll
    for (int k = 0; k < BATCH; ++k) {
        const int t  = tb_hi - k;
        const int i  = t * P + p;
        const int i1 = i + P;
        bf.d[k]  = dc2[i1];
        bf.r[k]  = rw2[i1];
        bf.st[k] = st2[i];
        bf.rb[k] = rb2[i];
        bf.tn[k] = tb2[i];
        bf.tv[k] = tv2[i];
        bf.vl[k] = vl2[i];
    }
}

__device__ __forceinline__ void compute_batch(
    const Buf& bf, int j, int p, int P, float2& acc,
    float2* __restrict__ ot2)
{
    const int tb_hi = 251 - 4 * j;
    #pragma unroll
    for (int k = 0; k < BATCH; ++k) {
        const int t = tb_hi - k;
        const bool nz = (t != 0);
        const bool lx = (bf.st[k].x == 2) || (nz && ((bf.rb[k].x | bf.tn[k].x) != 0));
        const bool ly = (bf.st[k].y == 2) || (nz && ((bf.rb[k].y | bf.tn[k].y) != 0));
        const float retx = fmaf(acc.x, bf.d[k].x * TD_GAMMA, bf.r[k].x);
        const float rety = fmaf(acc.y, bf.d[k].y * TD_GAMMA, bf.r[k].y);
        acc.x = lx ? bf.tv[k].x : retx;
        acc.y = ly ? bf.tv[k].y : rety;
        const float dx = retx - bf.vl[k].x;
        const float dy = rety - bf.vl[k].y;
        __stcs(&ot2[t * P + p], make_float2(dx * dx, dy * dy));
    }
}

__global__ void __launch_bounds__(64, 1) td_loss_kernel(
    const float* __restrict__ reward,
    const float* __restrict__ discount,
    const float* __restrict__ value,
    const float* __restrict__ target_value,
    const int*   __restrict__ step_type,
    const int*   __restrict__ rollout_b,
    const int*   __restrict__ train_b,
    float*       __restrict__ out,
    int B)
{
    const int p = blockIdx.x * blockDim.x + threadIdx.x;
    const int P = B >> 1;
    if (p >= P) return;

    const float2* __restrict__ rw2 = (const float2*)reward;
    const float2* __restrict__ dc2 = (const float2*)discount;
    const float2* __restrict__ vl2 = (const float2*)value;
    const float2* __restrict__ tv2 = (const float2*)target_value;
    const int2*   __restrict__ st2 = (const int2*)step_type;
    const int2*   __restrict__ rb2 = (const int2*)rollout_b;
    const int2*   __restrict__ tb2 = (const int2*)train_b;
    float2*       __restrict__ ot2 = (float2*)out;

    const int base = (TD_T - 1) * P + p;
    float2 acc = tv2[base];
    __stcs(&ot2[base], make_float2(0.0f, 0.0f));

    // Peel t = 254, 253, 252 (all t > 0 here).
    #pragma unroll
    for (int t = TD_T - 2; t >= 252; --t) {
        const int i  = t * P + p;
        const int i1 = i + P;
        const float2 d  = dc2[i1];
        const float2 r  = rw2[i1];
        const int2   st = st2[i];
        const int2   rb = rb2[i];
        const int2   tn = tb2[i];
        const float2 tv = tv2[i];
        const float2 vl = vl2[i];
        const bool lx = (st.x == 2) || ((rb.x | tn.x) != 0);
        const bool ly = (st.y == 2) || ((rb.y | tn.y) != 0);
        const float retx = fmaf(acc.x, d.x * TD_GAMMA, r.x);
        const float rety = fmaf(acc.y, d.y * TD_GAMMA, r.y);
        acc.x = lx ? tv.x : retx;
        acc.y = ly ? tv.y : rety;
        const float dx = retx - vl.x;
        const float dy = rety - vl.y;
        __stcs(&ot2[i], make_float2(dx * dx, dy * dy));
    }

    // Pipelined main loop: 63 batches (odd), unrolled by 2 with an epilogue.
    Buf bufA, bufB;
    load_batch(bufA, 0, p, P, rw2, dc2, vl2, tv2, st2, rb2, tb2);

    #pragma unroll 1
    for (int j = 0; j + 1 < NBATCH; j += 2) {
        load_batch(bufB, j + 1, p, P, rw2, dc2, vl2, tv2, st2, rb2, tb2);
        compute_batch(bufA, j, p, P, acc, ot2);
        if (j + 2 < NBATCH)
            load_batch(bufA, j + 2, p, P, rw2, dc2, vl2, tv2, st2, rb2, tb2);
        compute_batch(bufB, j + 1, p, P, acc, ot2);
    }
    // j == 62: final batch already resident in bufA.
    compute_batch(bufA, NBATCH - 1, p, P, acc, ot2);
}

extern "C" void kernel_launch(void* const* d_in, const int* in_sizes, int n_in,
                              void* d_out, int out_size)
{
    const float* reward       = (const float*)d_in[0];
    const float* discount     = (const float*)d_in[1];
    const float* value        = (const float*)d_in[2];
    const float* target_value = (const float*)d_in[3];
    const int*   step_type    = (const int*)d_in[4];
    const int*   rollout_b    = (const int*)d_in[5];
    const int*   train_b      = (const int*)d_in[6];
    float*       out          = (float*)d_out;

    const int B = in_sizes[0] / TD_T;
    const int pairs = B / 2;

    const int threads = 64;
    const int blocks  = (pairs + threads - 1) / threads;
    td_loss_kernel<<<blocks, threads>>>(reward, discount, value, target_value,
                                        step_type, rollout_b, train_b, out, B);
}